// round 7
// baseline (speedup 1.0000x reference)
#include <cuda_runtime.h>
#include <cstdint>

// Problem constants (fixed shape instance)
constexpr int B = 64;
constexpr int Q = 1024;
constexpr int N = 2048;
constexpr int C = 2048;
constexpr int P = 512;
constexpr int W = 256;
constexpr int HALF = W / 2;

// GEMM tiling: block tile 64b x 64j x 32k; grid = 8 j-tiles x 64 k-splits = 512
constexpr int KC  = 32;
constexpr int KS  = C / KC;   // 64
constexpr int JT  = 64;
constexpr int NJT = P / JT;   // 8
constexpr int RST = 36;       // tile row stride (floats) = 9 x 16B chunks (odd -> conflict-free)

// Scratch (__device__ globals: allocation-free rule)
__device__ float d_Hpart[KS * B * P];   // 8 MB split partials (L2-resident)
__device__ float d_partial[B * NJT];    // per-(b, j-tile) v_p.tanh partial dots

__device__ __forceinline__ void fma2(unsigned long long& d,
                                     unsigned long long a, unsigned long long b) {
    asm("fma.rn.f32x2 %0, %1, %2, %0;" : "+l"(d) : "l"(a), "l"(b));
}
__device__ __forceinline__ float hadd2(unsigned long long v) {
    float lo, hi;
    asm("mov.b64 {%0, %1}, %2;" : "=f"(lo), "=f"(hi) : "l"(v));
    return lo + hi;
}

// ---------------------------------------------------------------------------
// K1: Hpart[ks][b][j] = sum_{k in chunk ks} c_t[b,k] * w_p[j,k]
// grid 512 (jt = bid&7, ks = bid>>3), 128 threads.
// Row-major smem tiles (k contiguous); dot-product form with f32x2 k-pairs.
// Thread (bg = t&15, jg = t>>4): b in {bg+16i}, j in {4jg..+3, 32+4jg..+3}.
// ---------------------------------------------------------------------------
__global__ __launch_bounds__(128) void gemm_kernel(
    const float* __restrict__ c_t, const float* __restrict__ w_p)
{
    __shared__ float sc[B][RST];    // [b][k] row-major, KC=32 floats + pad
    __shared__ float sw[JT][RST];   // [j][k] row-major

    const int jt = blockIdx.x & (NJT - 1);
    const int ks = blockIdx.x >> 3;
    const int k0 = ks * KC;
    const int t  = threadIdx.x;

    // Fill tiles: straight float4 LDG -> float4 STS (no transpose).
    // idx covers 64 rows x 8 chunks; lanes 0..7 = one 128B row segment.
#pragma unroll
    for (int r = 0; r < 4; r++) {
        int idx = t + 128 * r;          // 0..511
        int row = idx >> 3, ch = idx & 7;
        float4 cv = *reinterpret_cast<const float4*>(c_t + (size_t)row * C + k0 + ch * 4);
        *reinterpret_cast<float4*>(&sc[row][ch * 4]) = cv;
        float4 wv = *reinterpret_cast<const float4*>(w_p + (size_t)(jt * JT + row) * C + k0 + ch * 4);
        *reinterpret_cast<float4*>(&sw[row][ch * 4]) = wv;
    }
    __syncthreads();

    const int bg = t & 15;
    const int jg = t >> 4;          // 0..7

    unsigned long long acc[4][8];   // [b_i][jj]: f32x2 partials (k-even, k-odd)
#pragma unroll
    for (int i = 0; i < 4; i++)
#pragma unroll
        for (int jj = 0; jj < 8; jj++) acc[i][jj] = 0ull;

#pragma unroll
    for (int kc = 0; kc < KC / 4; kc++) {
        ulonglong2 cv[4];
#pragma unroll
        for (int i = 0; i < 4; i++)
            cv[i] = *reinterpret_cast<const ulonglong2*>(&sc[bg + 16 * i][kc * 4]);
#pragma unroll
        for (int jj = 0; jj < 8; jj++) {
            int jr = (jj < 4) ? (4 * jg + jj) : (32 + 4 * jg + jj - 4);
            ulonglong2 wv = *reinterpret_cast<const ulonglong2*>(&sw[jr][kc * 4]);
#pragma unroll
            for (int i = 0; i < 4; i++) {
                fma2(acc[i][jj], cv[i].x, wv.x);
                fma2(acc[i][jj], cv[i].y, wv.y);
            }
        }
    }

    // Epilogue: horizontal add k-pairs, store two float4 quads per b-row.
#pragma unroll
    for (int i = 0; i < 4; i++) {
        int b = bg + 16 * i;
        size_t row = ((size_t)ks * B + b) * P + jt * JT;
        float4 q0 = make_float4(hadd2(acc[i][0]), hadd2(acc[i][1]),
                                hadd2(acc[i][2]), hadd2(acc[i][3]));
        float4 q1 = make_float4(hadd2(acc[i][4]), hadd2(acc[i][5]),
                                hadd2(acc[i][6]), hadd2(acc[i][7]));
        *reinterpret_cast<float4*>(&d_Hpart[row + 4 * jg])      = q0;
        *reinterpret_cast<float4*>(&d_Hpart[row + 32 + 4 * jg]) = q1;
    }
}

// ---------------------------------------------------------------------------
// K2: per (b, j-tile): Hsum = sum_ks Hpart; partial[b][jt] = sum_j v_p.tanh(Hsum)
// grid 512 (b = bid>>3, jt = bid&7), 256 thr.
// ---------------------------------------------------------------------------
__global__ __launch_bounds__(256) void reduce_head_kernel(
    const float* __restrict__ v_p)
{
    const int b  = blockIdx.x >> 3;
    const int jt = blockIdx.x & 7;
    const int t  = threadIdx.x;
    const int jq = t & 15;           // j-quad within 64-j tile
    const int g  = t >> 4;           // 0..15 ks-group

    float4 s = make_float4(0.f, 0.f, 0.f, 0.f);
#pragma unroll
    for (int i = 0; i < 4; i++) {
        int ks = g + 16 * i;
        float4 h = *reinterpret_cast<const float4*>(
            &d_Hpart[((size_t)ks * B + b) * P + jt * JT + jq * 4]);
        s.x += h.x; s.y += h.y; s.z += h.z; s.w += h.w;
    }
    __shared__ float4 hs[16][16];
    hs[g][jq] = s;
    __syncthreads();

    __shared__ float red[2];
    if (t < 64) {
        int quad = t >> 2, c = t & 3;
        float sum = 0.f;
#pragma unroll
        for (int g2 = 0; g2 < 16; g2++)
            sum += reinterpret_cast<const float*>(&hs[g2][quad])[c];
        float part = __ldg(v_p + jt * JT + t) * tanhf(sum);
#pragma unroll
        for (int o = 16; o > 0; o >>= 1)
            part += __shfl_down_sync(0xffffffffu, part, o);
        if ((t & 31) == 0) red[t >> 5] = part;
    }
    __syncthreads();
    if (t == 0) d_partial[b * NJT + jt] = red[0] + red[1];
}

// ---------------------------------------------------------------------------
// K4: head recompute (from 8 partials) + window sum with aligned float4 loads.
// s_t[b,q] = sum_w g[b,w] * q_i[b, q, base + w]
// grid (8, 64), 256 thr, 128 rows per block.
// ---------------------------------------------------------------------------
constexpr int GWN = 272;   // aligned weight span: 68 float4 (window 256 + <=16 slack)

__global__ __launch_bounds__(256) void window_sum_kernel(
    const float* __restrict__ q_i, float* __restrict__ out)
{
    __shared__ float s_gw[GWN];
    __shared__ float s_pt;
    __shared__ int   s_base, s_ba;

    const int b  = blockIdx.y;
    const int q0 = blockIdx.x * 128;
    const int t  = threadIdx.x;

    // --- head recompute (deterministic, identical across blocks of batch b) ---
    if (t == 0) {
        float x = 0.f;
#pragma unroll
        for (int i = 0; i < NJT; i++) x += d_partial[b * NJT + i];
        float loc = 1.f / (1.f + expf(-x));
        float pt  = loc * (float)(N - 1);      // loc * 2047
        int   p   = (int)rintf(pt);            // round-half-even == jnp.round
        int base = p - HALF;
        if (base < 0) base = 0;
        if (base > N - W) base = N - W;
        int ba = base & ~3;                    // float4-aligned read start
        if (ba > N - GWN) ba = N - GWN;        // keep 272-float read in-bounds
        s_pt = pt; s_base = base; s_ba = ba;
    }
    __syncthreads();

    const float pt  = s_pt;
    const int base  = s_base;
    const int ba    = s_ba;

    // weights over aligned span; zero outside the true 256-window
    if (t < GWN - 256) {   // t < 16: entries 256..271
        int j = 256 + t;
        int n = ba + j;
        float w = 0.f;
        if (n >= base && n < base + W) {
            float d = ((float)n - pt) * (1.0f / (float)HALF);
            w = expf(-2.f * d * d);
        }
        s_gw[j] = w;
    }
    {
        int n = ba + t;
        float w = 0.f;
        if (n >= base && n < base + W) {
            float d = ((float)n - pt) * (1.0f / (float)HALF);
            w = expf(-2.f * d * d);
        }
        s_gw[t] = w;
    }
    __syncthreads();

    const int warp = t >> 5, lane = t & 31;

    float4 g0 = *reinterpret_cast<const float4*>(&s_gw[8 * lane]);
    float4 g1 = *reinterpret_cast<const float4*>(&s_gw[8 * lane + 4]);
    float4 gx = make_float4(0.f, 0.f, 0.f, 0.f);
    if (lane < 4) gx = *reinterpret_cast<const float4*>(&s_gw[256 + 4 * lane]);

    const float* rowbase = q_i + ((size_t)b * Q + q0 + warp * 16) * N + ba;
    float* outbase = out + (size_t)b * Q + q0 + warp * 16;

#pragma unroll 2
    for (int r = 0; r < 16; r += 2) {
        const float4* r0 = reinterpret_cast<const float4*>(rowbase + (size_t)r * N);
        const float4* r1 = reinterpret_cast<const float4*>(rowbase + (size_t)(r + 1) * N);

        float4 a0 = __ldg(r0 + 2 * lane);
        float4 a1 = __ldg(r0 + 2 * lane + 1);
        float4 b0 = __ldg(r1 + 2 * lane);
        float4 b1 = __ldg(r1 + 2 * lane + 1);
        float4 ax = make_float4(0.f, 0.f, 0.f, 0.f);
        float4 bx = ax;
        if (lane < 4) { ax = __ldg(r0 + 64 + lane); bx = __ldg(r1 + 64 + lane); }

        float acc0 = a0.x * g0.x + a0.y * g0.y + a0.z * g0.z + a0.w * g0.w
                   + a1.x * g1.x + a1.y * g1.y + a1.z * g1.z + a1.w * g1.w
                   + ax.x * gx.x + ax.y * gx.y + ax.z * gx.z + ax.w * gx.w;
        float acc1 = b0.x * g0.x + b0.y * g0.y + b0.z * g0.z + b0.w * g0.w
                   + b1.x * g1.x + b1.y * g1.y + b1.z * g1.z + b1.w * g1.w
                   + bx.x * gx.x + bx.y * gx.y + bx.z * gx.z + bx.w * gx.w;

#pragma unroll
        for (int o = 16; o > 0; o >>= 1) {
            acc0 += __shfl_down_sync(0xffffffffu, acc0, o);
            acc1 += __shfl_down_sync(0xffffffffu, acc1, o);
        }
        if (lane == 0) { outbase[r] = acc0; outbase[r + 1] = acc1; }
    }
}

// ---------------------------------------------------------------------------
extern "C" void kernel_launch(void* const* d_in, const int* in_sizes, int n_in,
                              void* d_out, int out_size)
{
    const float* q_i = (const float*)d_in[0];  // (B,Q,N)
    const float* c_t = (const float*)d_in[1];  // (B,C)
    // d_in[2] = w_a : cancels (softmax over singleton axis == 1)
    const float* w_p = (const float*)d_in[3];  // (P,C)
    const float* v_p = (const float*)d_in[4];  // (1,P)
    float* out = (float*)d_out;                // (B,Q)

    gemm_kernel<<<NJT * KS, 128>>>(c_t, w_p);
    reduce_head_kernel<<<B * NJT, 256>>>(v_p);
    window_sum_kernel<<<dim3(Q / 128, B), 256>>>(q_i, out);
}

// round 8
// speedup vs baseline: 1.0918x; 1.0918x over previous
#include <cuda_runtime.h>
#include <cstdint>

// Problem constants (fixed shape instance)
constexpr int B = 64;
constexpr int Q = 1024;
constexpr int N = 2048;
constexpr int C = 2048;
constexpr int P = 512;
constexpr int W = 256;
constexpr int HALF = W / 2;

// GEMM: block tile 64b x 64j x 128k (4 pipelined sub-chunks of 32k)
constexpr int KC   = 32;            // sub-chunk k
constexpr int NCH  = 4;             // sub-chunks per block
constexpr int KSP  = C / (KC * NCH);// 16 k-splits
constexpr int JT   = 64;
constexpr int NJT  = P / JT;        // 8
constexpr int RST  = 36;            // smem row stride (floats), odd 16B-chunk stride
constexpr int TILE = 64 * RST;      // one matrix tile (floats)

// Scratch (__device__ globals: allocation-free rule)
__device__ float d_Hpart[KSP * B * P];  // 2 MB split partials (L2-resident)
__device__ float d_partial[B * NJT];    // per-(b, j-tile) v_p.tanh partial dots

__device__ __forceinline__ void fma2(unsigned long long& d,
                                     unsigned long long a, unsigned long long b) {
    asm("fma.rn.f32x2 %0, %1, %2, %0;" : "+l"(d) : "l"(a), "l"(b));
}
__device__ __forceinline__ float hadd2(unsigned long long v) {
    float lo, hi;
    asm("mov.b64 {%0, %1}, %2;" : "=f"(lo), "=f"(hi) : "l"(v));
    return lo + hi;
}
__device__ __forceinline__ unsigned smem_u32(const void* p) {
    unsigned a;
    asm("{ .reg .u64 t; cvta.to.shared.u64 t, %1; cvt.u32.u64 %0, t; }"
        : "=r"(a) : "l"(p));
    return a;
}
#define CP_ASYNC16(dst_u32, src_ptr) \
    asm volatile("cp.async.ca.shared.global [%0], [%1], 16;" \
                 :: "r"(dst_u32), "l"(src_ptr))
#define CP_COMMIT() asm volatile("cp.async.commit_group;")
#define CP_WAIT(n)  asm volatile("cp.async.wait_group %0;" :: "n"(n))

// ---------------------------------------------------------------------------
// K1: Hpart[ks][b][j] = sum_{k in 128-chunk ks} c_t[b,k] * w_p[j,k]
// grid 128 (jt = bid&7, ks = bid>>3), 256 threads.
// cp.async double-buffered over 4 sub-chunks; dot-form f32x2 compute.
// ---------------------------------------------------------------------------
__global__ __launch_bounds__(256) void gemm_kernel(
    const float* __restrict__ c_t, const float* __restrict__ w_p)
{
    __shared__ float sbuf[2][2 * TILE];   // [stage][c tile | w tile]

    const int jt = blockIdx.x & (NJT - 1);
    const int ks = blockIdx.x >> 3;
    const int kbase = ks * KC * NCH;
    const int t  = threadIdx.x;

    // Per-thread fill assignment: 2 float4 per matrix per stage.
    // idx in [0,512): row = idx>>3 (0..63), ch = idx&7.
    const int r0 = t >> 3,          c0 = t & 7;
    const int r1 = (t + 256) >> 3,  c1 = t & 7;   // (t+256)&7 == t&7

    const float* cg0 = c_t + (size_t)r0 * C + kbase + c0 * 4;
    const float* cg1 = c_t + (size_t)r1 * C + kbase + c1 * 4;
    const float* wg0 = w_p + (size_t)(jt * JT + r0) * C + kbase + c0 * 4;
    const float* wg1 = w_p + (size_t)(jt * JT + r1) * C + kbase + c1 * 4;

    unsigned sc_d0[2], sc_d1[2], sw_d0[2], sw_d1[2];
#pragma unroll
    for (int st = 0; st < 2; st++) {
        sc_d0[st] = smem_u32(&sbuf[st][r0 * RST + c0 * 4]);
        sc_d1[st] = smem_u32(&sbuf[st][r1 * RST + c1 * 4]);
        sw_d0[st] = smem_u32(&sbuf[st][TILE + r0 * RST + c0 * 4]);
        sw_d1[st] = smem_u32(&sbuf[st][TILE + r1 * RST + c1 * 4]);
    }

    // Prefetch chunk 0 into stage 0
    CP_ASYNC16(sc_d0[0], cg0);
    CP_ASYNC16(sc_d1[0], cg1);
    CP_ASYNC16(sw_d0[0], wg0);
    CP_ASYNC16(sw_d1[0], wg1);
    CP_COMMIT();

    const int bg = t & 15;          // b in {bg + 16*i}
    const int jg = t >> 4;          // j in {4*jg .. 4*jg+3}

    unsigned long long acc[4][4];   // [b_i][jj]: f32x2 k-pair partials
#pragma unroll
    for (int i = 0; i < 4; i++)
#pragma unroll
        for (int jj = 0; jj < 4; jj++) acc[i][jj] = 0ull;

#pragma unroll
    for (int s = 0; s < NCH; s++) {
        const int st = s & 1;
        if (s < NCH - 1) {          // prefetch next chunk into other stage
            const int koff = (s + 1) * KC;
            const int nst = st ^ 1;
            CP_ASYNC16(sc_d0[nst], cg0 + koff);
            CP_ASYNC16(sc_d1[nst], cg1 + koff);
            CP_ASYNC16(sw_d0[nst], wg0 + koff);
            CP_ASYNC16(sw_d1[nst], wg1 + koff);
            CP_COMMIT();
            CP_WAIT(1);
        } else {
            CP_WAIT(0);
        }
        __syncthreads();

        const float* sc = &sbuf[st][0];
        const float* sw = &sbuf[st][TILE];

#pragma unroll
        for (int kc = 0; kc < KC / 4; kc++) {
            ulonglong2 cv[4];
#pragma unroll
            for (int i = 0; i < 4; i++)
                cv[i] = *reinterpret_cast<const ulonglong2*>(
                    &sc[(bg + 16 * i) * RST + kc * 4]);
#pragma unroll
            for (int jj = 0; jj < 4; jj++) {
                ulonglong2 wv = *reinterpret_cast<const ulonglong2*>(
                    &sw[(4 * jg + jj) * RST + kc * 4]);
#pragma unroll
                for (int i = 0; i < 4; i++) {
                    fma2(acc[i][jj], cv[i].x, wv.x);
                    fma2(acc[i][jj], cv[i].y, wv.y);
                }
            }
        }
        __syncthreads();            // protect stage before next overwrite
    }

    // Epilogue: horizontal add k-pairs, one float4 per b-row.
#pragma unroll
    for (int i = 0; i < 4; i++) {
        int b = bg + 16 * i;
        size_t row = ((size_t)ks * B + b) * P + jt * JT + 4 * jg;
        *reinterpret_cast<float4*>(&d_Hpart[row]) =
            make_float4(hadd2(acc[i][0]), hadd2(acc[i][1]),
                        hadd2(acc[i][2]), hadd2(acc[i][3]));
    }
}

// ---------------------------------------------------------------------------
// K2: per (b, j-tile): Hsum = sum_ks Hpart; partial[b][jt] = sum_j v_p.tanh(Hsum)
// grid 512 (b = bid>>3, jt = bid&7), 256 thr (one float4 per thread).
// ---------------------------------------------------------------------------
__global__ __launch_bounds__(256) void reduce_head_kernel(
    const float* __restrict__ v_p)
{
    const int b  = blockIdx.x >> 3;
    const int jt = blockIdx.x & 7;
    const int t  = threadIdx.x;
    const int jq = t & 15;           // j-quad within 64-j tile
    const int g  = t >> 4;           // split 0..15

    float4 h = *reinterpret_cast<const float4*>(
        &d_Hpart[((size_t)g * B + b) * P + jt * JT + jq * 4]);

    __shared__ float4 hs[16][16];
    hs[g][jq] = h;
    __syncthreads();

    __shared__ float red[2];
    if (t < 64) {
        int quad = t >> 2, c = t & 3;
        float sum = 0.f;
#pragma unroll
        for (int g2 = 0; g2 < 16; g2++)
            sum += reinterpret_cast<const float*>(&hs[g2][quad])[c];
        float part = __ldg(v_p + jt * JT + t) * tanhf(sum);
#pragma unroll
        for (int o = 16; o > 0; o >>= 1)
            part += __shfl_down_sync(0xffffffffu, part, o);
        if ((t & 31) == 0) red[t >> 5] = part;
    }
    __syncthreads();
    if (t == 0) d_partial[b * NJT + jt] = red[0] + red[1];
}

// ---------------------------------------------------------------------------
// K4: head recompute (from 8 partials) + window sum with aligned float4 loads.
// s_t[b,q] = sum_w g[b,w] * q_i[b, q, base + w]
// grid (8, 64), 256 thr, 128 rows per block.
// ---------------------------------------------------------------------------
constexpr int GWN = 272;   // aligned weight span: 68 float4

__global__ __launch_bounds__(256) void window_sum_kernel(
    const float* __restrict__ q_i, float* __restrict__ out)
{
    __shared__ float s_gw[GWN];
    __shared__ float s_pt;
    __shared__ int   s_base, s_ba;

    const int b  = blockIdx.y;
    const int q0 = blockIdx.x * 128;
    const int t  = threadIdx.x;

    if (t == 0) {
        float x = 0.f;
#pragma unroll
        for (int i = 0; i < NJT; i++) x += d_partial[b * NJT + i];
        float loc = 1.f / (1.f + expf(-x));
        float pt  = loc * (float)(N - 1);      // loc * 2047
        int   p   = (int)rintf(pt);            // round-half-even == jnp.round
        int base = p - HALF;
        if (base < 0) base = 0;
        if (base > N - W) base = N - W;
        int ba = base & ~3;                    // float4-aligned read start
        if (ba > N - GWN) ba = N - GWN;
        s_pt = pt; s_base = base; s_ba = ba;
    }
    __syncthreads();

    const float pt  = s_pt;
    const int base  = s_base;
    const int ba    = s_ba;

    if (t < GWN - 256) {   // entries 256..271
        int j = 256 + t;
        int n = ba + j;
        float w = 0.f;
        if (n >= base && n < base + W) {
            float d = ((float)n - pt) * (1.0f / (float)HALF);
            w = expf(-2.f * d * d);
        }
        s_gw[j] = w;
    }
    {
        int n = ba + t;
        float w = 0.f;
        if (n >= base && n < base + W) {
            float d = ((float)n - pt) * (1.0f / (float)HALF);
            w = expf(-2.f * d * d);
        }
        s_gw[t] = w;
    }
    __syncthreads();

    const int warp = t >> 5, lane = t & 31;

    float4 g0 = *reinterpret_cast<const float4*>(&s_gw[8 * lane]);
    float4 g1 = *reinterpret_cast<const float4*>(&s_gw[8 * lane + 4]);
    float4 gx = make_float4(0.f, 0.f, 0.f, 0.f);
    if (lane < 4) gx = *reinterpret_cast<const float4*>(&s_gw[256 + 4 * lane]);

    const float* rowbase = q_i + ((size_t)b * Q + q0 + warp * 16) * N + ba;
    float* outbase = out + (size_t)b * Q + q0 + warp * 16;

#pragma unroll 2
    for (int r = 0; r < 16; r += 2) {
        const float4* r0 = reinterpret_cast<const float4*>(rowbase + (size_t)r * N);
        const float4* r1 = reinterpret_cast<const float4*>(rowbase + (size_t)(r + 1) * N);

        float4 a0 = __ldg(r0 + 2 * lane);
        float4 a1 = __ldg(r0 + 2 * lane + 1);
        float4 b0 = __ldg(r1 + 2 * lane);
        float4 b1 = __ldg(r1 + 2 * lane + 1);
        float4 ax = make_float4(0.f, 0.f, 0.f, 0.f);
        float4 bx = ax;
        if (lane < 4) { ax = __ldg(r0 + 64 + lane); bx = __ldg(r1 + 64 + lane); }

        float acc0 = a0.x * g0.x + a0.y * g0.y + a0.z * g0.z + a0.w * g0.w
                   + a1.x * g1.x + a1.y * g1.y + a1.z * g1.z + a1.w * g1.w
                   + ax.x * gx.x + ax.y * gx.y + ax.z * gx.z + ax.w * gx.w;
        float acc1 = b0.x * g0.x + b0.y * g0.y + b0.z * g0.z + b0.w * g0.w
                   + b1.x * g1.x + b1.y * g1.y + b1.z * g1.z + b1.w * g1.w
                   + bx.x * gx.x + bx.y * gx.y + bx.z * gx.z + bx.w * gx.w;

#pragma unroll
        for (int o = 16; o > 0; o >>= 1) {
            acc0 += __shfl_down_sync(0xffffffffu, acc0, o);
            acc1 += __shfl_down_sync(0xffffffffu, acc1, o);
        }
        if (lane == 0) { outbase[r] = acc0; outbase[r + 1] = acc1; }
    }
}

// ---------------------------------------------------------------------------
extern "C" void kernel_launch(void* const* d_in, const int* in_sizes, int n_in,
                              void* d_out, int out_size)
{
    const float* q_i = (const float*)d_in[0];  // (B,Q,N)
    const float* c_t = (const float*)d_in[1];  // (B,C)
    // d_in[2] = w_a : cancels (softmax over singleton axis == 1)
    const float* w_p = (const float*)d_in[3];  // (P,C)
    const float* v_p = (const float*)d_in[4];  // (1,P)
    float* out = (float*)d_out;                // (B,Q)

    gemm_kernel<<<NJT * KSP, 256>>>(c_t, w_p);
    reduce_head_kernel<<<B * NJT, 256>>>(v_p);
    window_sum_kernel<<<dim3(Q / 128, B), 256>>>(q_i, out);
}